// round 13
// baseline (speedup 1.0000x reference)
#include <cuda_runtime.h>

// ---------------- geometry ----------------
#define T_STEPS 15
#define H1 1020            // conv1 output (== input spatial)
#define HP1 511            // pool1 output
#define H2 501             // conv2 output
#define HP2 251            // pool2 output
#define H3 249             // conv3 output
#define N3 (2*H3*H3)       // 124002
#define PTOT (15*N3)
#define WINBASE (2*PTOT)

// ---------------- scratch ----------------
__device__ unsigned char g_tau_in[2 * H1 * H1];
__device__ unsigned char g_tau1[4 * H1 * H1];
__device__ unsigned char g_tp1[4 * HP1 * HP1];
__device__ unsigned char g_tau2[8 * H2 * H2];
__device__ unsigned char g_tp2[8 * HP2 * HP2];
__device__ long long     g_total_ll[N3];

__constant__ float c_w2[8 * 4 * 15 * 15];
__constant__ float c_w3[2 * 8 * 7 * 7];

// conv1 masks are DETERMINISTIC (fixed arrays in the reference __init__):
// w = 0.25 + 0.5*mask  ->  w*4 = 1 + 2*mask. Same for both input channels.
// Encoded as 25-bit integers (bit i = ky*5+kx); constexpr device function so
// fully-unrolled loops fold each access into an immediate.
__device__ __forceinline__ constexpr bool c1m(int c, int i) {
    // d0: row ky=2 ; d1: kx<2 ; d2: m2 ; d3: m3
    constexpr unsigned int m[4] = {0x7C00u, 0x318C63u, 0x10638C1u, 0x133990u};
    return ((m[c] >> i) & 1u) != 0u;
}

// ---------------- K1: input first-spike times (float4 vectorized) -------------
__global__ void k_tau_in(const float4* __restrict__ in) {
    const int plane4 = 2 * H1 * H1 / 4;          // 520200
    int i = blockIdx.x * blockDim.x + threadIdx.x;
    if (i >= plane4) return;
    float sx = 0.f, sy = 0.f, sz = 0.f, sw = 0.f;
#pragma unroll
    for (int t = 0; t < T_STEPS; t++) {
        float4 v = in[t * plane4 + i];
        sx += v.x; sy += v.y; sz += v.z; sw += v.w;
    }
    uchar4 r;
    r.x = (unsigned char)(15.5f - sx);
    r.y = (unsigned char)(15.5f - sy);
    r.z = (unsigned char)(15.5f - sz);
    r.w = (unsigned char)(15.5f - sw);
    ((uchar4*)g_tau_in)[i] = r;
}

// ---------------- K2: conv1 via shared + masked SWAR histograms ---------------
// pot4_c(t) = Scum(t) + 2*Mcum_c(t):
//   S   = histogram of ALL 50 taps (both channels), weight 1  (shared by c)
//   M_c = histogram of masked taps only (5/5/9/9 positions x 2 channels)
// 16 bins packed as 4 x uint32 (8-bit lanes; S<=100, M<=18). Exact integers.
// Measured 66.3us (R12).
__global__ void k_conv1() {
    __shared__ unsigned char s[2][12][36];
    int tx = threadIdx.x, ty = threadIdx.y;
    int tid = ty * 32 + tx;
    int x0 = blockIdx.x * 32, y0 = blockIdx.y * 8;

    for (int i = tid; i < 2 * 12 * 36; i += 256) {
        int ch = i / 432, r = i % 432, yy = r / 36, xx = r % 36;
        int gy = y0 - 2 + yy, gx = x0 - 2 + xx;
        ((unsigned char*)s)[i] = (gy >= 0 && gy < H1 && gx >= 0 && gx < H1)
                                     ? g_tau_in[ch * H1 * H1 + gy * H1 + gx]
                                     : (unsigned char)15;
    }
    __syncthreads();
    int x = x0 + tx, y = y0 + ty;
    if (x >= H1 || y >= H1) return;

    unsigned int S[4] = {0u, 0u, 0u, 0u};
    unsigned int M[4][4];
#pragma unroll
    for (int c = 0; c < 4; c++)
#pragma unroll
        for (int k = 0; k < 4; k++) M[c][k] = 0u;

#pragma unroll
    for (int ky = 0; ky < 5; ky++) {
#pragma unroll
        for (int kx = 0; kx < 5; kx++) {
            int v0 = s[0][ty + ky][tx + kx];
            int v1 = s[1][ty + ky][tx + kx];
            unsigned int u0 = 1u << ((v0 & 3) * 8);
            unsigned int u1 = 1u << ((v1 & 3) * 8);
            int k0 = v0 >> 2, k1 = v1 >> 2;
#pragma unroll
            for (int k = 0; k < 4; k++) {
                S[k] += (k0 == k) ? u0 : 0u;
                S[k] += (k1 == k) ? u1 : 0u;
            }
#pragma unroll
            for (int c = 0; c < 4; c++) {
                if (c1m(c, ky * 5 + kx)) {        // compile-time constant
#pragma unroll
                    for (int k = 0; k < 4; k++) {
                        M[c][k] += (k0 == k) ? u0 : 0u;
                        M[c][k] += (k1 == k) ? u1 : 0u;
                    }
                }
            }
        }
    }

    int scum = 0;
    int mcum[4] = {0, 0, 0, 0};
    int tau[4] = {15, 15, 15, 15};
#pragma unroll
    for (int t = 0; t < 15; t++) {
        scum += (int)((S[t >> 2] >> ((t & 3) * 8)) & 0xFFu);
#pragma unroll
        for (int c = 0; c < 4; c++) {
            mcum[c] += (int)((M[c][t >> 2] >> ((t & 3) * 8)) & 0xFFu);
            if (tau[c] == 15 && scum + 2 * mcum[c] >= 20) tau[c] = t;
        }
    }
#pragma unroll
    for (int c = 0; c < 4; c++)
        g_tau1[c * H1 * H1 + y * H1 + x] = (unsigned char)tau[c];
}

// ---------------- K2b: pool1 ----------------
__global__ void k_pool1() {
    int gi = blockIdx.x * blockDim.x + threadIdx.x;
    if (gi >= 4 * HP1 * HP1) return;
    int c = gi / (HP1 * HP1);
    int r = gi % (HP1 * HP1);
    int py = r / HP1, px = r % HP1;
    int m = 15;
    for (int dy = 0; dy < 2; dy++) {
        int y = 2 * py - 1 + dy;
        if (y < 0 || y >= H1) continue;
        for (int dx = 0; dx < 2; dx++) {
            int x = 2 * px - 1 + dx;
            if (x < 0 || x >= H1) continue;
            m = min(m, (int)g_tau1[c * H1 * H1 + y * H1 + x]);
        }
    }
    g_tp1[gi] = (unsigned char)m;
}

// ---------------- K3: conv2 (15x15x4, thr 50) -> tau2 ----------------
// Proven smem histogram scatter (R6/R7/R10, ~549us at the crossbar floor):
// word-vectorized tau reads, per-thread bin columns (stride 256, conflict-free).
// Do not add control flow (R8/R9 both regressed).
#define TY3 8
#define TILEH 22
#define TILEWP 48
__global__ void k_conv2() {
    __shared__ unsigned char s_tau[4 * TILEH * TILEWP];
    __shared__ float sdelta[16 * 256];
    int tx = threadIdx.x, ty = threadIdx.y;
    int tid = ty * 32 + tx;
    int c2 = blockIdx.z;
    int y0 = blockIdx.y * TY3, x0 = blockIdx.x * 32;

    for (int i = tid; i < 4 * TILEH * TILEWP; i += 256) {
        int ci = i / (TILEH * TILEWP);
        int rr = i % (TILEH * TILEWP);
        int yy = rr / TILEWP, xx = rr % TILEWP;
        int gy = y0 - 2 + yy, gx = x0 - 2 + xx;
        s_tau[i] = (xx < 46 && gy >= 0 && gy < HP1 && gx >= 0 && gx < HP1)
                       ? g_tp1[(ci * HP1 + gy) * HP1 + gx]
                       : (unsigned char)15;
    }
    __syncthreads();

#pragma unroll
    for (int t = 0; t < 16; t++) sdelta[t * 256 + tid] = 0.f;

    const unsigned int* srow32 = (const unsigned int*)s_tau;
    int j0 = tx >> 2;
    int off = (tx & 3) * 8;

    for (int ci = 0; ci < 4; ci++) {
        for (int ky = 0; ky < 15; ky++) {
            int rw = (ci * TILEH + ty + ky) * (TILEWP / 4);
            unsigned int q0 = srow32[rw + j0];
            unsigned int q1 = srow32[rw + j0 + 1];
            unsigned int q2 = srow32[rw + j0 + 2];
            unsigned int q3 = srow32[rw + j0 + 3];
            unsigned int q4 = srow32[rw + j0 + 4];
            unsigned int a0 = __funnelshift_r(q0, q1, off);
            unsigned int a1 = __funnelshift_r(q1, q2, off);
            unsigned int a2 = __funnelshift_r(q2, q3, off);
            unsigned int a3 = __funnelshift_r(q3, q4, off);
            const float* wr = &c_w2[((c2 * 4 + ci) * 15 + ky) * 15];
#pragma unroll
            for (int kx = 0; kx < 15; kx++) {
                unsigned int aw = (kx < 4) ? a0 : (kx < 8) ? a1 : (kx < 12) ? a2 : a3;
                int v = (int)((aw >> ((kx & 3) * 8)) & 0xFFu);
                sdelta[v * 256 + tid] += wr[kx];
            }
        }
    }

    float cum = 0.f;
    int tau = 15;
#pragma unroll
    for (int t = 0; t < 15; t++) {
        cum += sdelta[t * 256 + tid];
        if (tau == 15 && cum >= 50.0f) tau = t;
    }
    int y = y0 + ty, x = x0 + tx;
    if (y < H2 && x < H2) g_tau2[(c2 * H2 + y) * H2 + x] = (unsigned char)tau;
}

// ---------------- K4: pool2 ----------------
__global__ void k_pool2() {
    int gi = blockIdx.x * blockDim.x + threadIdx.x;
    if (gi >= 8 * HP2 * HP2) return;
    int c = gi / (HP2 * HP2);
    int r = gi % (HP2 * HP2);
    int py = r / HP2, px = r % HP2;
    int m = 15;
    for (int dy = 0; dy < 2; dy++) {
        int y = 2 * py - 1 + dy;
        if (y < 0 || y >= H2) continue;
        for (int dx = 0; dx < 2; dx++) {
            int x = 2 * px - 1 + dx;
            if (x < 0 || x >= H2) continue;
            m = min(m, (int)g_tau2[(c * H2 + y) * H2 + x]);
        }
    }
    g_tp2[gi] = (unsigned char)m;
}

// ---------------- K5: conv3 (7x7x8, thr 40) + fire + outputs + fused total ------
// Phase 1: fp32 histogram (raw c_w3, validated numerics) -> cum, tau3, spk/pot.
// Phase 2: exact int64 total via closed form over a second tap walk (warm L1):
//   total = sum_taps w * coef(v), coef = (15 - max(v,tau3)) + [v<=14]*tau3*(15-tau3)
//   with w quantized rint(w*2^24): exact integer ordering for the winner argmax.
// (R6/R7-proven fused form.)
__global__ void k_conv3_total(float* __restrict__ out) {
    __shared__ float sdelta[16 * 256];
    int tid = threadIdx.x;
    int gi = blockIdx.x * 256 + tid;
#pragma unroll
    for (int t = 0; t < 16; t++) sdelta[t * 256 + tid] = 0.f;
    if (gi >= N3) return;
    int c = gi / (H3 * H3);
    int r = gi % (H3 * H3);
    int y = r / H3, x = r % H3;

    for (int ci = 0; ci < 8; ci++) {
        for (int ky = 0; ky < 7; ky++) {
            int iy = y + ky - 2;
            if (iy < 0 || iy >= HP2) continue;
#pragma unroll
            for (int kx = 0; kx < 7; kx++) {
                int ix = x + kx - 2;
                if (ix < 0 || ix >= HP2) continue;
                int tau = g_tp2[(ci * HP2 + iy) * HP2 + ix];
                sdelta[tau * 256 + tid] += c_w3[((c * 8 + ci) * 7 + ky) * 7 + kx];
            }
        }
    }

    float cum = 0.f;
    int tau3 = 15;
#pragma unroll
    for (int t = 0; t < 15; t++) {
        cum += sdelta[t * 256 + tid];
        bool s = (cum >= 40.0f);
        if (tau3 == 15 && s) tau3 = t;
        out[t * N3 + gi] = s ? 1.0f : 0.f;              // spk
        out[PTOT + t * N3 + gi] = s ? cum : 0.f;        // thresholded pot
    }

    // ---- fused exact-int total ----
    if (tau3 >= 15) { g_total_ll[gi] = 0; return; }
    int K = tau3 * (15 - tau3);
    long long tot = 0;
    for (int ci = 0; ci < 8; ci++) {
        for (int ky = 0; ky < 7; ky++) {
            int iy = y + ky - 2;
            if (iy < 0 || iy >= HP2) continue;
#pragma unroll
            for (int kx = 0; kx < 7; kx++) {
                int ix = x + kx - 2;
                if (ix < 0 || ix >= HP2) continue;
                int v = g_tp2[(ci * HP2 + iy) * HP2 + ix];
                int wi = (int)rintf(c_w3[((c * 8 + ci) * 7 + ky) * 7 + kx] * 16777216.f);
                int m = (v > tau3) ? v : tau3;
                int coef = (15 - m) + ((v <= 14) ? K : 0);
                tot += (long long)wi * coef;
            }
        }
    }
    g_total_ll[gi] = tot;
}

// ---------------- K6: k-winners (k=2, r=5), packed u64 keys ----------------
__global__ void k_winners(float* __restrict__ out) {
    __shared__ unsigned long long sk[1024];
    __shared__ int s_w[3];
    __shared__ int s_valid;
    int tid = threadIdx.x;

    for (int p = 0; p < 2; p++) {
        unsigned long long best = 0ull;
        for (int i = tid; i < N3; i += 1024) {
            long long v = g_total_ll[i];
            if (p == 1 && s_valid) {
                int c = i / (H3 * H3);
                int r = i % (H3 * H3);
                int yy = r / H3, xx = r % H3;
                int dy = yy - s_w[1], dx = xx - s_w[2];
                if (c == s_w[0] && dy >= -5 && dy <= 5 && dx >= -5 && dx <= 5) v = 0;
            }
            if (v > 0) {
                // max value, then min index: totals < 2^39, index < 2^17
                unsigned long long key =
                    ((unsigned long long)v << 17) | (unsigned long long)(131071 - i);
                if (key > best) best = key;
            }
        }
        sk[tid] = best;
        __syncthreads();
        for (int s = 512; s > 0; s >>= 1) {
            if (tid < s) {
                if (sk[tid + s] > sk[tid]) sk[tid] = sk[tid + s];
            }
            __syncthreads();
        }
        if (tid == 0) {
            unsigned long long b = sk[0];
            int valid = (b != 0ull) ? 1 : 0;
            int i = valid ? (131071 - (int)(b & 0x1FFFFull)) : 0;
            int c = i / (H3 * H3);
            int r = i % (H3 * H3);
            int yy = r / H3, xx = r % H3;
            out[WINBASE + p * 3 + 0] = valid ? (float)c : -1.f;
            out[WINBASE + p * 3 + 1] = valid ? (float)yy : -1.f;
            out[WINBASE + p * 3 + 2] = valid ? (float)xx : -1.f;
            if (p == 0) { s_valid = valid; s_w[0] = c; s_w[1] = yy; s_w[2] = xx; }
        }
        __syncthreads();
    }
}

// ---------------- launcher ----------------
extern "C" void kernel_launch(void* const* d_in, const int* in_sizes, int n_in,
                              void* d_out, int out_size) {
    const float* inp = (const float*)d_in[0];
    cudaMemcpyToSymbolAsync(c_w2, d_in[2], 8 * 4 * 15 * 15 * sizeof(float), 0,
                            cudaMemcpyDeviceToDevice, 0);
    cudaMemcpyToSymbolAsync(c_w3, d_in[3], 2 * 8 * 7 * 7 * sizeof(float), 0,
                            cudaMemcpyDeviceToDevice, 0);
    float* out = (float*)d_out;

    const int plane4 = 2 * H1 * H1 / 4;
    k_tau_in<<<(plane4 + 255) / 256, 256>>>((const float4*)inp);    // launch 1
    k_conv1<<<dim3(32, 128), dim3(32, 8)>>>();                      // launch 2
    k_pool1<<<(4 * HP1 * HP1 + 255) / 256, 256>>>();                // launch 3
    k_conv2<<<dim3((H2 + 31) / 32, (H2 + TY3 - 1) / TY3, 8),        // launch 4 (profiled)
              dim3(32, TY3)>>>();
    k_pool2<<<(8 * HP2 * HP2 + 255) / 256, 256>>>();                // launch 5
    k_conv3_total<<<(N3 + 255) / 256, 256>>>(out);                  // launch 6
    k_winners<<<1, 1024>>>(out);                                    // launch 7
}

// round 14
// speedup vs baseline: 1.6471x; 1.6471x over previous
#include <cuda_runtime.h>

// ---------------- geometry ----------------
#define T_STEPS 15
#define H1 1020            // conv1 output (== input spatial)
#define HP1 511            // pool1 output
#define H2 501             // conv2 output
#define HP2 251            // pool2 output
#define H3 249             // conv3 output
#define N3 (2*H3*H3)       // 124002
#define PTOT (15*N3)
#define WINBASE (2*PTOT)

// ---------------- scratch ----------------
__device__ unsigned char g_tau_in[2 * H1 * H1];
__device__ unsigned char g_tau1[4 * H1 * H1];
__device__ unsigned char g_tp1[4 * HP1 * HP1];
__device__ unsigned char g_tau2[8 * H2 * H2];
__device__ unsigned char g_tp2[8 * HP2 * HP2];
__device__ long long     g_total_ll[N3];

__constant__ float c_w2[8 * 4 * 15 * 15];
__constant__ float c_w3[2 * 8 * 7 * 7];

// conv1 masks are DETERMINISTIC (fixed arrays in the reference __init__):
// w = 0.25 + 0.5*mask  ->  w*4 = 1 + 2*mask. Same for both input channels.
__device__ __forceinline__ constexpr bool c1m(int c, int i) {
    // d0: row ky=2 ; d1: kx<2 ; d2: m2 ; d3: m3
    constexpr unsigned int m[4] = {0x7C00u, 0x318C63u, 0x10638C1u, 0x133990u};
    return ((m[c] >> i) & 1u) != 0u;
}

// ---------------- K1: input first-spike times (float4 vectorized) -------------
__global__ void k_tau_in(const float4* __restrict__ in) {
    const int plane4 = 2 * H1 * H1 / 4;          // 520200
    int i = blockIdx.x * blockDim.x + threadIdx.x;
    if (i >= plane4) return;
    float sx = 0.f, sy = 0.f, sz = 0.f, sw = 0.f;
#pragma unroll
    for (int t = 0; t < T_STEPS; t++) {
        float4 v = in[t * plane4 + i];
        sx += v.x; sy += v.y; sz += v.z; sw += v.w;
    }
    uchar4 r;
    r.x = (unsigned char)(15.5f - sx);
    r.y = (unsigned char)(15.5f - sy);
    r.z = (unsigned char)(15.5f - sz);
    r.w = (unsigned char)(15.5f - sw);
    ((uchar4*)g_tau_in)[i] = r;
}

// ---------------- K2: conv1 via shared + masked SWAR histograms ---------------
// Measured 66.3us (R12). Exact integers -> bit-identical tau1.
__global__ void k_conv1() {
    __shared__ unsigned char s[2][12][36];
    int tx = threadIdx.x, ty = threadIdx.y;
    int tid = ty * 32 + tx;
    int x0 = blockIdx.x * 32, y0 = blockIdx.y * 8;

    for (int i = tid; i < 2 * 12 * 36; i += 256) {
        int ch = i / 432, r = i % 432, yy = r / 36, xx = r % 36;
        int gy = y0 - 2 + yy, gx = x0 - 2 + xx;
        ((unsigned char*)s)[i] = (gy >= 0 && gy < H1 && gx >= 0 && gx < H1)
                                     ? g_tau_in[ch * H1 * H1 + gy * H1 + gx]
                                     : (unsigned char)15;
    }
    __syncthreads();
    int x = x0 + tx, y = y0 + ty;
    if (x >= H1 || y >= H1) return;

    unsigned int S[4] = {0u, 0u, 0u, 0u};
    unsigned int M[4][4];
#pragma unroll
    for (int c = 0; c < 4; c++)
#pragma unroll
        for (int k = 0; k < 4; k++) M[c][k] = 0u;

#pragma unroll
    for (int ky = 0; ky < 5; ky++) {
#pragma unroll
        for (int kx = 0; kx < 5; kx++) {
            int v0 = s[0][ty + ky][tx + kx];
            int v1 = s[1][ty + ky][tx + kx];
            unsigned int u0 = 1u << ((v0 & 3) * 8);
            unsigned int u1 = 1u << ((v1 & 3) * 8);
            int k0 = v0 >> 2, k1 = v1 >> 2;
#pragma unroll
            for (int k = 0; k < 4; k++) {
                S[k] += (k0 == k) ? u0 : 0u;
                S[k] += (k1 == k) ? u1 : 0u;
            }
#pragma unroll
            for (int c = 0; c < 4; c++) {
                if (c1m(c, ky * 5 + kx)) {        // compile-time constant
#pragma unroll
                    for (int k = 0; k < 4; k++) {
                        M[c][k] += (k0 == k) ? u0 : 0u;
                        M[c][k] += (k1 == k) ? u1 : 0u;
                    }
                }
            }
        }
    }

    int scum = 0;
    int mcum[4] = {0, 0, 0, 0};
    int tau[4] = {15, 15, 15, 15};
#pragma unroll
    for (int t = 0; t < 15; t++) {
        scum += (int)((S[t >> 2] >> ((t & 3) * 8)) & 0xFFu);
#pragma unroll
        for (int c = 0; c < 4; c++) {
            mcum[c] += (int)((M[c][t >> 2] >> ((t & 3) * 8)) & 0xFFu);
            if (tau[c] == 15 && scum + 2 * mcum[c] >= 20) tau[c] = t;
        }
    }
#pragma unroll
    for (int c = 0; c < 4; c++)
        g_tau1[c * H1 * H1 + y * H1 + x] = (unsigned char)tau[c];
}

// ---------------- K2b: pool1 ----------------
__global__ void k_pool1() {
    int gi = blockIdx.x * blockDim.x + threadIdx.x;
    if (gi >= 4 * HP1 * HP1) return;
    int c = gi / (HP1 * HP1);
    int r = gi % (HP1 * HP1);
    int py = r / HP1, px = r % HP1;
    int m = 15;
    for (int dy = 0; dy < 2; dy++) {
        int y = 2 * py - 1 + dy;
        if (y < 0 || y >= H1) continue;
        for (int dx = 0; dx < 2; dx++) {
            int x = 2 * px - 1 + dx;
            if (x < 0 || x >= H1) continue;
            m = min(m, (int)g_tau1[c * H1 * H1 + y * H1 + x]);
        }
    }
    g_tp1[gi] = (unsigned char)m;
}

// ---------------- K3: conv2 (15x15x4, thr 50) -> tau2; 2 channels/block -------
// Histogram scatter with float2 bins serving TWO c2 channels per block:
// crossbar bytes identical to the proven single-channel version (LDS.64+STS.64
// for 2ch == 2x LDS.32+STS.32), but tau decode, s_tau loads and tile fills
// halve. Per-channel add order unchanged -> bit-identical tau2.
#define TY3 8
#define TILEH 22
#define TILEWP 48
__global__ void k_conv2() {
    __shared__ unsigned char s_tau[4 * TILEH * TILEWP];
    __shared__ float2 sdelta[16 * 256];
    int tx = threadIdx.x, ty = threadIdx.y;
    int tid = ty * 32 + tx;
    int c2a = blockIdx.z * 2;          // channels c2a and c2a+1
    int y0 = blockIdx.y * TY3, x0 = blockIdx.x * 32;

    for (int i = tid; i < 4 * TILEH * TILEWP; i += 256) {
        int ci = i / (TILEH * TILEWP);
        int rr = i % (TILEH * TILEWP);
        int yy = rr / TILEWP, xx = rr % TILEWP;
        int gy = y0 - 2 + yy, gx = x0 - 2 + xx;
        s_tau[i] = (xx < 46 && gy >= 0 && gy < HP1 && gx >= 0 && gx < HP1)
                       ? g_tp1[(ci * HP1 + gy) * HP1 + gx]
                       : (unsigned char)15;
    }
    __syncthreads();

#pragma unroll
    for (int t = 0; t < 16; t++) sdelta[t * 256 + tid] = make_float2(0.f, 0.f);

    const unsigned int* srow32 = (const unsigned int*)s_tau;
    int j0 = tx >> 2;
    int off = (tx & 3) * 8;

    for (int ci = 0; ci < 4; ci++) {
        for (int ky = 0; ky < 15; ky++) {
            int rw = (ci * TILEH + ty + ky) * (TILEWP / 4);
            unsigned int q0 = srow32[rw + j0];
            unsigned int q1 = srow32[rw + j0 + 1];
            unsigned int q2 = srow32[rw + j0 + 2];
            unsigned int q3 = srow32[rw + j0 + 3];
            unsigned int q4 = srow32[rw + j0 + 4];
            unsigned int a0 = __funnelshift_r(q0, q1, off);
            unsigned int a1 = __funnelshift_r(q1, q2, off);
            unsigned int a2 = __funnelshift_r(q2, q3, off);
            unsigned int a3 = __funnelshift_r(q3, q4, off);
            const float* wra = &c_w2[((c2a * 4 + ci) * 15 + ky) * 15];
            const float* wrb = &c_w2[(((c2a + 1) * 4 + ci) * 15 + ky) * 15];
#pragma unroll
            for (int kx = 0; kx < 15; kx++) {
                unsigned int aw = (kx < 4) ? a0 : (kx < 8) ? a1 : (kx < 12) ? a2 : a3;
                int v = (int)((aw >> ((kx & 3) * 8)) & 0xFFu);
                float2 d = sdelta[v * 256 + tid];
                d.x += wra[kx];
                d.y += wrb[kx];
                sdelta[v * 256 + tid] = d;
            }
        }
    }

    float cuma = 0.f, cumb = 0.f;
    int taua = 15, taub = 15;
#pragma unroll
    for (int t = 0; t < 15; t++) {
        float2 d = sdelta[t * 256 + tid];
        cuma += d.x;
        cumb += d.y;
        if (taua == 15 && cuma >= 50.0f) taua = t;
        if (taub == 15 && cumb >= 50.0f) taub = t;
    }
    int y = y0 + ty, x = x0 + tx;
    if (y < H2 && x < H2) {
        g_tau2[(c2a * H2 + y) * H2 + x] = (unsigned char)taua;
        g_tau2[((c2a + 1) * H2 + y) * H2 + x] = (unsigned char)taub;
    }
}

// ---------------- K4: pool2 ----------------
__global__ void k_pool2() {
    int gi = blockIdx.x * blockDim.x + threadIdx.x;
    if (gi >= 8 * HP2 * HP2) return;
    int c = gi / (HP2 * HP2);
    int r = gi % (HP2 * HP2);
    int py = r / HP2, px = r % HP2;
    int m = 15;
    for (int dy = 0; dy < 2; dy++) {
        int y = 2 * py - 1 + dy;
        if (y < 0 || y >= H2) continue;
        for (int dx = 0; dx < 2; dx++) {
            int x = 2 * px - 1 + dx;
            if (x < 0 || x >= H2) continue;
            m = min(m, (int)g_tau2[(c * H2 + y) * H2 + x]);
        }
    }
    g_tp2[gi] = (unsigned char)m;
}

// ---------------- K5: conv3 (7x7x8, thr 40) + fire + outputs + fused total ------
__global__ void k_conv3_total(float* __restrict__ out) {
    __shared__ float sdelta[16 * 256];
    int tid = threadIdx.x;
    int gi = blockIdx.x * 256 + tid;
#pragma unroll
    for (int t = 0; t < 16; t++) sdelta[t * 256 + tid] = 0.f;
    if (gi >= N3) return;
    int c = gi / (H3 * H3);
    int r = gi % (H3 * H3);
    int y = r / H3, x = r % H3;

    for (int ci = 0; ci < 8; ci++) {
        for (int ky = 0; ky < 7; ky++) {
            int iy = y + ky - 2;
            if (iy < 0 || iy >= HP2) continue;
#pragma unroll
            for (int kx = 0; kx < 7; kx++) {
                int ix = x + kx - 2;
                if (ix < 0 || ix >= HP2) continue;
                int tau = g_tp2[(ci * HP2 + iy) * HP2 + ix];
                sdelta[tau * 256 + tid] += c_w3[((c * 8 + ci) * 7 + ky) * 7 + kx];
            }
        }
    }

    float cum = 0.f;
    int tau3 = 15;
#pragma unroll
    for (int t = 0; t < 15; t++) {
        cum += sdelta[t * 256 + tid];
        bool s = (cum >= 40.0f);
        if (tau3 == 15 && s) tau3 = t;
        out[t * N3 + gi] = s ? 1.0f : 0.f;              // spk
        out[PTOT + t * N3 + gi] = s ? cum : 0.f;        // thresholded pot
    }

    // ---- fused exact-int total ----
    if (tau3 >= 15) { g_total_ll[gi] = 0; return; }
    int K = tau3 * (15 - tau3);
    long long tot = 0;
    for (int ci = 0; ci < 8; ci++) {
        for (int ky = 0; ky < 7; ky++) {
            int iy = y + ky - 2;
            if (iy < 0 || iy >= HP2) continue;
#pragma unroll
            for (int kx = 0; kx < 7; kx++) {
                int ix = x + kx - 2;
                if (ix < 0 || ix >= HP2) continue;
                int v = g_tp2[(ci * HP2 + iy) * HP2 + ix];
                int wi = (int)rintf(c_w3[((c * 8 + ci) * 7 + ky) * 7 + kx] * 16777216.f);
                int m = (v > tau3) ? v : tau3;
                int coef = (15 - m) + ((v <= 14) ? K : 0);
                tot += (long long)wi * coef;
            }
        }
    }
    g_total_ll[gi] = tot;
}

// ---------------- K6: k-winners (k=2, r=5), packed u64 keys ----------------
__global__ void k_winners(float* __restrict__ out) {
    __shared__ unsigned long long sk[1024];
    __shared__ int s_w[3];
    __shared__ int s_valid;
    int tid = threadIdx.x;

    for (int p = 0; p < 2; p++) {
        unsigned long long best = 0ull;
        for (int i = tid; i < N3; i += 1024) {
            long long v = g_total_ll[i];
            if (p == 1 && s_valid) {
                int c = i / (H3 * H3);
                int r = i % (H3 * H3);
                int yy = r / H3, xx = r % H3;
                int dy = yy - s_w[1], dx = xx - s_w[2];
                if (c == s_w[0] && dy >= -5 && dy <= 5 && dx >= -5 && dx <= 5) v = 0;
            }
            if (v > 0) {
                // max value, then min index: totals < 2^39, index < 2^17
                unsigned long long key =
                    ((unsigned long long)v << 17) | (unsigned long long)(131071 - i);
                if (key > best) best = key;
            }
        }
        sk[tid] = best;
        __syncthreads();
        for (int s = 512; s > 0; s >>= 1) {
            if (tid < s) {
                if (sk[tid + s] > sk[tid]) sk[tid] = sk[tid + s];
            }
            __syncthreads();
        }
        if (tid == 0) {
            unsigned long long b = sk[0];
            int valid = (b != 0ull) ? 1 : 0;
            int i = valid ? (131071 - (int)(b & 0x1FFFFull)) : 0;
            int c = i / (H3 * H3);
            int r = i % (H3 * H3);
            int yy = r / H3, xx = r % H3;
            out[WINBASE + p * 3 + 0] = valid ? (float)c : -1.f;
            out[WINBASE + p * 3 + 1] = valid ? (float)yy : -1.f;
            out[WINBASE + p * 3 + 2] = valid ? (float)xx : -1.f;
            if (p == 0) { s_valid = valid; s_w[0] = c; s_w[1] = yy; s_w[2] = xx; }
        }
        __syncthreads();
    }
}

// ---------------- launcher ----------------
extern "C" void kernel_launch(void* const* d_in, const int* in_sizes, int n_in,
                              void* d_out, int out_size) {
    const float* inp = (const float*)d_in[0];
    cudaMemcpyToSymbolAsync(c_w2, d_in[2], 8 * 4 * 15 * 15 * sizeof(float), 0,
                            cudaMemcpyDeviceToDevice, 0);
    cudaMemcpyToSymbolAsync(c_w3, d_in[3], 2 * 8 * 7 * 7 * sizeof(float), 0,
                            cudaMemcpyDeviceToDevice, 0);
    float* out = (float*)d_out;

    const int plane4 = 2 * H1 * H1 / 4;
    k_tau_in<<<(plane4 + 255) / 256, 256>>>((const float4*)inp);    // launch 1
    k_conv1<<<dim3(32, 128), dim3(32, 8)>>>();                      // launch 2
    k_pool1<<<(4 * HP1 * HP1 + 255) / 256, 256>>>();                // launch 3
    k_conv2<<<dim3((H2 + 31) / 32, (H2 + TY3 - 1) / TY3, 4),        // launch 4 (profiled)
              dim3(32, TY3)>>>();
    k_pool2<<<(8 * HP2 * HP2 + 255) / 256, 256>>>();                // launch 5
    k_conv3_total<<<(N3 + 255) / 256, 256>>>(out);                  // launch 6
    k_winners<<<1, 1024>>>(out);                                    // launch 7
}